// round 15
// baseline (speedup 1.0000x reference)
#include <cuda_runtime.h>
#include <cuda_fp16.h>
#include <math.h>
#include <stdint.h>

// Problem constants
#define NBAT   16384
#define NMAST  8
#define NB     (NBAT * NMAST)   // 131072
#define IN_DIM 128
#define H_DIM  256
#define A_DIM  64
#define NA_DIM 32

// ---------------- scratch ----------------------------------------------------
__device__ uint16_t g_moH [(size_t)NB * IN_DIM];
__device__ uint16_t g_hidH[(size_t)NB * H_DIM];
__device__ uint16_t g_xH  [(size_t)NB * H_DIM];   // encoder out, fp16
__device__ uint16_t g_eH  [(size_t)NB * A_DIM];   // attention out, fp16
__device__ uint16_t g_hH  [(size_t)NB * H_DIM];   // h_out copy, fp16
__device__ uint16_t g_wencH[256 * 128];
__device__ uint16_t g_wqkvH[3 * 64 * 256];        // [192][256]: q|k|v rows
__device__ uint16_t g_wcatH[1024 * 448];          // gate-interleaved [h*4+g][448]
__device__ uint16_t g_wdecH[32 * 256];

// ---------------- helpers ----------------------------------------------------
__device__ __forceinline__ uint16_t f2h(float f) {
    return __half_as_ushort(__float2half_rn(f));
}
__device__ __forceinline__ void mma16(float* c, const uint32_t* a, const uint32_t* b) {
    asm volatile(
        "mma.sync.aligned.m16n8k16.row.col.f32.f16.f16.f32 "
        "{%0,%1,%2,%3},{%4,%5,%6,%7},{%8,%9},{%0,%1,%2,%3};\n"
        : "+f"(c[0]), "+f"(c[1]), "+f"(c[2]), "+f"(c[3])
        : "r"(a[0]), "r"(a[1]), "r"(a[2]), "r"(a[3]), "r"(b[0]), "r"(b[1]));
}
__device__ __forceinline__ void ldsm4(uint32_t* r, uint32_t saddr) {
    asm volatile("ldmatrix.sync.aligned.m8n8.x4.shared.b16 {%0,%1,%2,%3}, [%4];"
        : "=r"(r[0]), "=r"(r[1]), "=r"(r[2]), "=r"(r[3]) : "r"(saddr));
}
__device__ __forceinline__ void cp16(uint32_t dst, const void* src) {
    asm volatile("cp.async.cg.shared.global [%0], [%1], 16;\n" :: "r"(dst), "l"(src));
}
__device__ __forceinline__ void cp_commit() {
    asm volatile("cp.async.commit_group;\n");
}
template<int N>
__device__ __forceinline__ void cp_wait() {
    asm volatile("cp.async.wait_group %0;\n" :: "n"(N));
}
__device__ __forceinline__ float sigf(float x) { return 1.f / (1.f + expf(-x)); }

struct GP {
    const uint16_t *A;
    const uint16_t *B0;
    const float *bias0;
    float *out0;
    uint16_t *outH;
};

// ============================================================================
// fused QKV GEMM + masked self-attention (unchanged)
// ============================================================================
#define QK_ITERS 8
#define QK_S 3
#define QK_ASTAGE 10240u
#define QK_BSTAGE 15360u
#define QK_SMEM 104448u

__global__ void __launch_bounds__(256, 1) qkv_attn_kernel(
    const uint16_t* __restrict__ xH, const uint16_t* __restrict__ wqkvH,
    const float* __restrict__ bv, uint16_t* __restrict__ eH)
{
    extern __shared__ uint32_t smem_u[];
    const uint32_t As_sh = (uint32_t)__cvta_generic_to_shared(smem_u);
    const uint32_t Bs_sh = As_sh + QK_S * QK_ASTAGE;

    const int tid  = threadIdx.x;
    const int lane = tid & 31, warp = tid >> 5;
    const int wr = warp >> 1, wc = warp & 1;
    const int qq = lane & 3, rr = lane >> 2;
    const int m0 = blockIdx.x * 128;

    const int a_r = lane & 15, a_h = lane >> 4;
    const int b_g = lane >> 3, b_rl = lane & 7;
    const int b_row = (b_g >> 1) * 8 + b_rl;
    const int b_k16 = (b_g & 1) * 16;

    auto issue = [&](int it, int s) {
        uint32_t Ast = As_sh + (uint32_t)s * QK_ASTAGE;
        uint32_t Bst = Bs_sh + (uint32_t)s * QK_BSTAGE;
        #pragma unroll
        for (int t5 = 0; t5 < 5; ++t5) {
            int t = tid + t5 * 256;
            if (t < 512) {
                int row = t >> 2, seg = t & 3;
                cp16(Ast + (uint32_t)(row * 80 + seg * 16),
                     xH + (size_t)(m0 + row) * 256 + it * 32 + seg * 8);
            } else {
                int u = t - 512;
                int row = u >> 2, seg = u & 3;
                cp16(Bst + (uint32_t)(row * 80 + seg * 16),
                     wqkvH + (size_t)row * 256 + it * 32 + seg * 8);
            }
        }
    };

    float acc[2][12][4];
    #pragma unroll
    for (int i = 0; i < 2; i++)
        #pragma unroll
        for (int j = 0; j < 12; j++)
            #pragma unroll
            for (int t = 0; t < 4; t++) acc[i][j][t] = 0.f;

    issue(0, 0); cp_commit();
    issue(1, 1); cp_commit();

    #pragma unroll
    for (int it = 0; it < QK_ITERS; ++it) {
        const int s  = it % QK_S;
        const int s2 = (it + 2) % QK_S;
        cp_wait<1>();
        __syncthreads();
        if (it + 2 < QK_ITERS) issue(it + 2, s2);
        cp_commit();

        const uint32_t Ab = As_sh + (uint32_t)s * QK_ASTAGE;
        const uint32_t Bb = Bs_sh + (uint32_t)s * QK_BSTAGE;
        #pragma unroll
        for (int ph = 0; ph < 2; ++ph) {
            uint32_t af[2][4], bf[12][2];
            #pragma unroll
            for (int mi = 0; mi < 2; ++mi)
                ldsm4(af[mi], Ab + (uint32_t)((wr * 32 + mi * 16 + a_r) * 80
                                              + ph * 32 + a_h * 16));
            #pragma unroll
            for (int pi = 0; pi < 6; ++pi)
                ldsm4(&bf[2 * pi][0], Bb + (uint32_t)((wc * 96 + pi * 16 + b_row) * 80
                                                      + ph * 32 + b_k16));
            #pragma unroll
            for (int mi = 0; mi < 2; ++mi)
                #pragma unroll
                for (int ni = 0; ni < 12; ++ni)
                    mma16(acc[mi][ni], af[mi], bf[ni]);
        }
    }
    cp_wait<0>();
    __syncthreads();

    float* sq = (float*)smem_u;
    float* sk = sq + 128 * 68;
    float* sv = sk + 128 * 68;
    #pragma unroll
    for (int mi = 0; mi < 2; ++mi)
        #pragma unroll
        for (int ni = 0; ni < 12; ++ni) {
            int col = wc * 96 + ni * 8 + qq * 2;
            int mat = col >> 6, loc = col & 63;
            int m = wr * 32 + mi * 16 + rr;
            float v0 = acc[mi][ni][0], v1 = acc[mi][ni][1];
            float v2 = acc[mi][ni][2], v3 = acc[mi][ni][3];
            float* dst = (mat == 0) ? sq : (mat == 1) ? sk : sv;
            if (mat == 2) {
                float b0 = bv[loc], b1 = bv[loc + 1];
                v0 = fmaxf(v0 + b0, 0.f); v1 = fmaxf(v1 + b1, 0.f);
                v2 = fmaxf(v2 + b0, 0.f); v3 = fmaxf(v3 + b1, 0.f);
            }
            dst[m * 68 + loc]           = v0;
            dst[m * 68 + loc + 1]       = v1;
            dst[(m + 8) * 68 + loc]     = v2;
            dst[(m + 8) * 68 + loc + 1] = v3;
        }
    __syncthreads();

    const int j  = lane & 7;
    const int i0 = lane >> 3;
    const int i1 = i0 + 4;
    const unsigned fm = 0xffffffffu;
    #pragma unroll
    for (int gi = 0; gi < 2; ++gi) {
        const int r0 = (warp * 2 + gi) * 8;
        float s0 = 0.f, s1 = 0.f;
        #pragma unroll
        for (int a = 0; a < A_DIM; a++) {
            float kv = sk[(r0 + j) * 68 + a];
            s0 = fmaf(sq[(r0 + i0) * 68 + a], kv, s0);
            s1 = fmaf(sq[(r0 + i1) * 68 + a], kv, s1);
        }
        s0 *= 0.125f; s1 *= 0.125f;
        if (i0 == j) s0 = -1e9f;
        if (i1 == j) s1 = -1e9f;

        float mm0 = s0, mm1 = s1;
        #pragma unroll
        for (int o = 4; o >= 1; o >>= 1) {
            mm0 = fmaxf(mm0, __shfl_xor_sync(fm, mm0, o));
            mm1 = fmaxf(mm1, __shfl_xor_sync(fm, mm1, o));
        }
        float e0 = expf(s0 - mm0), e1 = expf(s1 - mm1);
        float z0 = e0, z1 = e1;
        #pragma unroll
        for (int o = 4; o >= 1; o >>= 1) {
            z0 += __shfl_xor_sync(fm, z0, o);
            z1 += __shfl_xor_sync(fm, z1, o);
        }
        float w0 = e0 / z0, w1 = e1 / z1;

        float av[8][2] = {};
        #pragma unroll
        for (int i = 0; i < 8; i++) {
            #pragma unroll
            for (int jj = 0; jj < 8; jj++) {
                float wij = __shfl_sync(fm, (i < 4) ? w0 : w1, ((i & 3) << 3) + jj);
                av[i][0] = fmaf(wij, sv[(r0 + jj) * 68 + lane],      av[i][0]);
                av[i][1] = fmaf(wij, sv[(r0 + jj) * 68 + lane + 32], av[i][1]);
            }
        }
        #pragma unroll
        for (int i = 0; i < 8; i++) {
            uint16_t* er = eH + (size_t)(m0 + r0 + i) * 64;
            er[lane]      = f2h(av[i][0]);
            er[lane + 32] = f2h(av[i][1]);
        }
    }
}

// ============================================================================
// gates: 64x64 CTA tile, 128 threads, 8 CTAs/SM, S=2 double-buffer,
//        k32 chunks + fused LSTM. Stage: rows 0-63 A, 64-127 B. 80B stride.
// ============================================================================
#define G_ITERS 14
#define G_S 2
#define G_ROW 80u
#define G_STAGE (128u * G_ROW)     // 10240 B

__global__ void __launch_bounds__(128, 8) gates_kernel(
    const uint16_t* __restrict__ moH, const uint16_t* __restrict__ eH,
    const uint16_t* __restrict__ hidH, const uint16_t* __restrict__ wcatH,
    const float* __restrict__ bih, const float* __restrict__ bhh,
    const float* __restrict__ cell,
    float* __restrict__ h_out, float* __restrict__ c_out,
    uint16_t* __restrict__ hH)
{
    extern __shared__ uint32_t smem_u[];
    const uint32_t base_sh = (uint32_t)__cvta_generic_to_shared(smem_u);

    const int tid  = threadIdx.x;
    const int lane = tid & 31, warp = tid >> 5;
    const int wr = warp >> 1, wc = warp & 1;      // 2 m-groups x 2 n-groups
    const int q  = lane & 3,  rr = lane >> 2;
    const int m0 = blockIdx.y * 64;
    const int bx = blockIdx.x;                    // 16 n-tiles (64 cols = 16 h)

    const int a_r = lane & 15, a_h = lane >> 4;
    const int b_g = lane >> 3, b_rl = lane & 7;
    const int b_row = (b_g >> 1) * 8 + b_rl;
    const int b_k16 = (b_g & 1) * 16;

    // load tasks: r=0,1 -> A rows 0..63 ; r=2,3 -> B rows 64..127
    const int aRow0 = tid >> 2,         aSeg0 = tid & 3;
    const int aRow1 = (tid + 128) >> 2, aSeg1 = (tid + 128) & 3;
    const uint32_t aOff0 = (uint32_t)aRow0 * G_ROW + (uint32_t)aSeg0 * 16;
    const uint32_t aOff1 = (uint32_t)aRow1 * G_ROW + (uint32_t)aSeg1 * 16;
    const uint16_t* bSrc[2];
    uint32_t bOff[2];
    #pragma unroll
    for (int r = 0; r < 2; ++r) {
        int idx = tid + 256 + r * 128;            // 256..511
        int row = idx >> 2, seg = idx & 3;        // rows 64..127
        bOff[r] = (uint32_t)row * G_ROW + (uint32_t)seg * 16;
        bSrc[r] = wcatH + (size_t)(bx * 64 + row - 64) * 448 + seg * 8;
    }

    auto issue = [&](int it, int s) {
        uint32_t st = base_sh + (uint32_t)s * G_STAGE;
        const uint16_t *s0, *s1;
        if (it < 4)      { s0 = moH  + (size_t)(m0 + aRow0) * 128 + it * 32 + aSeg0 * 8;
                           s1 = moH  + (size_t)(m0 + aRow1) * 128 + it * 32 + aSeg1 * 8; }
        else if (it < 6) { s0 = eH   + (size_t)(m0 + aRow0) * 64 + (it - 4) * 32 + aSeg0 * 8;
                           s1 = eH   + (size_t)(m0 + aRow1) * 64 + (it - 4) * 32 + aSeg1 * 8; }
        else             { s0 = hidH + (size_t)(m0 + aRow0) * 256 + (it - 6) * 32 + aSeg0 * 8;
                           s1 = hidH + (size_t)(m0 + aRow1) * 256 + (it - 6) * 32 + aSeg1 * 8; }
        cp16(st + aOff0, s0);
        cp16(st + aOff1, s1);
        cp16(st + bOff[0], bSrc[0] + it * 32);
        cp16(st + bOff[1], bSrc[1] + it * 32);
    };

    float acc[2][4][4];
    #pragma unroll
    for (int i = 0; i < 2; i++)
        #pragma unroll
        for (int j = 0; j < 4; j++)
            #pragma unroll
            for (int t = 0; t < 4; t++) acc[i][j][t] = 0.f;

    issue(0, 0); cp_commit();
    issue(1, 1); cp_commit();

    #pragma unroll
    for (int it = 0; it < G_ITERS; ++it) {
        const int s = it % G_S;
        cp_wait<1>();
        __syncthreads();          // chunk `it` resident & visible

        const uint32_t St = base_sh + (uint32_t)s * G_STAGE;
        #pragma unroll
        for (int ph = 0; ph < 2; ++ph) {
            uint32_t af[2][4], bf[4][2];
            #pragma unroll
            for (int mi = 0; mi < 2; ++mi)
                ldsm4(af[mi], St + (uint32_t)((wr * 32 + mi * 16 + a_r) * G_ROW
                                              + ph * 32 + a_h * 16));
            #pragma unroll
            for (int pi = 0; pi < 2; ++pi)
                ldsm4(&bf[2 * pi][0], St + (uint32_t)((64 + wc * 32 + pi * 16 + b_row) * G_ROW
                                                      + ph * 32 + b_k16));
            #pragma unroll
            for (int mi = 0; mi < 2; ++mi)
                #pragma unroll
                for (int ni = 0; ni < 4; ++ni)
                    mma16(acc[mi][ni], af[mi], bf[ni]);
        }

        __syncthreads();          // all reads of stage `s` done before refill
        if (it + 2 < G_ITERS) issue(it + 2, s);
        cp_commit();              // unconditional: keeps wait<1> bookkeeping exact
    }
    cp_wait<0>();
    __syncthreads();

    // ---- fused LSTM epilogue (64 rows x 16 h per CTA) ----
    float* smc = (float*)smem_u;            // cell tile [64][17]
    float* smr = smc + 64 * 17;             // h tile   [64][17]
    const int h0 = bx * 16;
    for (int i = tid; i < 1024; i += 128) {
        int m = i >> 4, h = i & 15;
        smc[m * 17 + h] = cell[(size_t)(m0 + m) * 256 + h0 + h];
    }
    __syncthreads();

    const bool even = (q & 1) == 0;
    #pragma unroll
    for (int ni = 0; ni < 4; ++ni) {
        int nb = wc * 32 + ni * 8;
        int h_loc = (nb >> 2) + (q >> 1);        // 0..15
        int hg = h0 + h_loc;
        int g0 = (q & 1) * 2;
        float bb0 = bih[g0 * 256 + hg] + bhh[g0 * 256 + hg];
        float bb1 = bih[(g0 + 1) * 256 + hg] + bhh[(g0 + 1) * 256 + hg];
        #pragma unroll
        for (int mi = 0; mi < 2; ++mi) {
            float c0 = acc[mi][ni][0] + bb0, c1 = acc[mi][ni][1] + bb1;
            float c2 = acc[mi][ni][2] + bb0, c3 = acc[mi][ni][3] + bb1;
            float p0 = __shfl_xor_sync(~0u, c0, 1);
            float p1 = __shfl_xor_sync(~0u, c1, 1);
            float p2 = __shfl_xor_sync(~0u, c2, 1);
            float p3 = __shfl_xor_sync(~0u, c3, 1);
            if (even) {
                int ml = wr * 32 + mi * 16 + rr;
                float cp0 = smc[ml * 17 + h_loc];
                float cp1 = smc[(ml + 8) * 17 + h_loc];
                float cn0 = sigf(c1) * cp0 + sigf(c0) * tanhf(p0);
                float hn0 = sigf(p1) * tanhf(cn0);
                float cn1 = sigf(c3) * cp1 + sigf(c2) * tanhf(p2);
                float hn1 = sigf(p3) * tanhf(cn1);
                acc[mi][ni][0] = hn0; acc[mi][ni][1] = cn0;
                acc[mi][ni][2] = hn1; acc[mi][ni][3] = cn1;
            }
        }
    }
    __syncthreads();
    #pragma unroll
    for (int ni = 0; ni < 4; ++ni) {
        int nb = wc * 32 + ni * 8;
        int h_loc = (nb >> 2) + (q >> 1);
        #pragma unroll
        for (int mi = 0; mi < 2; ++mi) {
            if (even) {
                int ml = wr * 32 + mi * 16 + rr;
                smr[ml * 17 + h_loc]       = acc[mi][ni][0];
                smc[ml * 17 + h_loc]       = acc[mi][ni][1];
                smr[(ml + 8) * 17 + h_loc] = acc[mi][ni][2];
                smc[(ml + 8) * 17 + h_loc] = acc[mi][ni][3];
            }
        }
    }
    __syncthreads();
    for (int i = tid; i < 1024; i += 128) {
        int m = i >> 4, h = i & 15;
        size_t off = (size_t)(m0 + m) * 256 + h0 + h;
        float hv = smr[m * 17 + h];
        h_out[off] = hv;
        c_out[off] = smc[m * 17 + h];
        hH[off]    = f2h(hv);
    }
}

// ============================================================================
// GEMM template: MODE 0 encoder (BN=128), MODE 3 decoder (BN=32)
// ============================================================================
template<int MODE>
__global__ void __launch_bounds__(256, 2) gemm_f16(GP p) {
    constexpr int BN = (MODE == 3) ? 32 : 128;
    constexpr int WC = (MODE == 3) ? 1  : 4;
    constexpr int WR = 8 / WC;
    constexpr int MT = 8 / WR;
    constexpr int NT = 4;
    constexpr int K  = (MODE == 0) ? 128 : 256;
    constexpr int ITERS = K / 32;
    constexpr int WTM = MT * 16;
    constexpr int S   = 3;
    constexpr int AK  = (MODE == 0) ? 128 : 256;
    constexpr int BKH = K;
    constexpr uint32_t ASTAGE_B = 128 * 80;
    constexpr uint32_t BSTAGE_B = BN * 80;

    extern __shared__ uint32_t smem_u[];
    const uint32_t As_sh = (uint32_t)__cvta_generic_to_shared(smem_u);
    const uint32_t Bs_sh = As_sh + S * ASTAGE_B;

    const int tid  = threadIdx.x;
    const int lane = tid & 31, warp = tid >> 5;
    const int wr = warp / WC, wc = warp % WC;
    const int q  = lane & 3,  rr = lane >> 2;
    const int m0 = blockIdx.y * 128;
    const int bx = blockIdx.x;

    const int arow = tid >> 2;
    const int aseg = tid & 3;
    const uint32_t tOff = (uint32_t)(arow * 80 + aseg * 16);

    const uint16_t* pA = p.A + (size_t)(m0 + arow) * AK + aseg * 8;
    const uint16_t* pB;
    if constexpr (MODE == 0) pB = p.B0 + (size_t)(bx * 128 + arow) * 128 + aseg * 8;
    else                     pB = p.B0 + (size_t)arow * 256 + aseg * 8;

    auto issue = [&](int it, int s) {
        uint32_t ad = As_sh + (uint32_t)s * ASTAGE_B + tOff;
        uint32_t bd = Bs_sh + (uint32_t)s * BSTAGE_B + tOff;
        const uint16_t* a0 = pA + it * 32;
        cp16(ad, a0);
        cp16(ad + 64 * 80, a0 + (size_t)64 * AK);
        if constexpr (BN == 128) {
            cp16(bd, pB + it * 32);
            cp16(bd + 64 * 80, pB + (size_t)64 * BKH + it * 32);
        } else {
            if (tid < 128) cp16(bd, pB + it * 32);
        }
    };

    float acc[MT][NT][4];
    #pragma unroll
    for (int i = 0; i < MT; i++)
        #pragma unroll
        for (int j = 0; j < NT; j++)
            #pragma unroll
            for (int t = 0; t < 4; t++) acc[i][j][t] = 0.f;

    const int a_r = lane & 15, a_h = lane >> 4;
    const int b_g = lane >> 3, b_rl = lane & 7;
    const int b_row = (b_g >> 1) * 8 + b_rl;
    const int b_k16 = (b_g & 1) * 16;

    issue(0, 0); cp_commit();
    issue(1, 1); cp_commit();

    #pragma unroll
    for (int it = 0; it < ITERS; ++it) {
        const int s  = it % S;
        const int s2 = (it + 2) % S;
        cp_wait<1>();
        __syncthreads();
        if (it + 2 < ITERS) issue(it + 2, s2);
        cp_commit();

        const uint32_t Ab = As_sh + (uint32_t)s * ASTAGE_B;
        const uint32_t Bb = Bs_sh + (uint32_t)s * BSTAGE_B;
        #pragma unroll
        for (int ph = 0; ph < 2; ++ph) {
            uint32_t af[MT][4], bf[NT][2];
            #pragma unroll
            for (int mi = 0; mi < MT; ++mi)
                ldsm4(af[mi], Ab + (uint32_t)((wr * WTM + mi * 16 + a_r) * 80
                                              + ph * 32 + a_h * 16));
            #pragma unroll
            for (int pi = 0; pi < NT / 2; ++pi)
                ldsm4(&bf[2 * pi][0], Bb + (uint32_t)((wc * 32 + pi * 16 + b_row) * 80
                                                      + ph * 32 + b_k16));
            #pragma unroll
            for (int mi = 0; mi < MT; ++mi)
                #pragma unroll
                for (int ni = 0; ni < NT; ++ni)
                    mma16(acc[mi][ni], af[mi], bf[ni]);
        }
    }
    cp_wait<0>();
    __syncthreads();

    if constexpr (MODE == 0) {
        #pragma unroll
        for (int mi = 0; mi < MT; ++mi)
            #pragma unroll
            for (int ni = 0; ni < NT; ++ni) {
                int n = bx * 128 + wc * 32 + ni * 8 + q * 2;
                int m = m0 + wr * WTM + mi * 16 + rr;
                float b0v = p.bias0[n], b1v = p.bias0[n + 1];
                __half2 h0 = __floats2half2_rn(fmaxf(acc[mi][ni][0] + b0v, 0.f),
                                               fmaxf(acc[mi][ni][1] + b1v, 0.f));
                __half2 h1 = __floats2half2_rn(fmaxf(acc[mi][ni][2] + b0v, 0.f),
                                               fmaxf(acc[mi][ni][3] + b1v, 0.f));
                *(__half2*)(p.outH + (size_t)m * 256 + n) = h0;
                *(__half2*)(p.outH + (size_t)(m + 8) * 256 + n) = h1;
            }
    } else {
        #pragma unroll
        for (int mi = 0; mi < MT; ++mi)
            #pragma unroll
            for (int ni = 0; ni < NT; ++ni) {
                int n = ni * 8 + q * 2;
                int m = m0 + wr * WTM + mi * 16 + rr;
                float b0v = p.bias0[n], b1v = p.bias0[n + 1];
                *(float2*)(p.out0 + (size_t)m * 32 + n) =
                    make_float2(acc[mi][ni][0] + b0v, acc[mi][ni][1] + b1v);
                *(float2*)(p.out0 + (size_t)(m + 8) * 32 + n) =
                    make_float2(acc[mi][ni][2] + b0v, acc[mi][ni][3] + b1v);
            }
    }
}

// ---------------- pack/convert prologue --------------------------------------
__global__ void pack_kernel(const float* __restrict__ mo, const float* __restrict__ hid,
                            const float* __restrict__ Wenc,
                            const float* __restrict__ Wq, const float* __restrict__ Wk,
                            const float* __restrict__ Wv,
                            const float* __restrict__ Wih, const float* __restrict__ Whh,
                            const float* __restrict__ Wdec,
                            uint16_t* __restrict__ moH, uint16_t* __restrict__ hidH,
                            uint16_t* __restrict__ wencH, uint16_t* __restrict__ wqkvH,
                            uint16_t* __restrict__ wcatH, uint16_t* __restrict__ wdecH)
{
    const int stride = gridDim.x * blockDim.x;
    const int g = blockIdx.x * blockDim.x + threadIdx.x;
    auto cvt4 = [](float4 v) -> uint2 {
        __half2 h01 = __floats2half2_rn(v.x, v.y);
        __half2 h23 = __floats2half2_rn(v.z, v.w);
        return make_uint2(*(uint32_t*)&h01, *(uint32_t*)&h23);
    };
    {
        const float4* s4 = (const float4*)mo;
        uint2* d4 = (uint2*)moH;
        for (size_t i = g; i < (size_t)NB * 128 / 4; i += stride) d4[i] = cvt4(s4[i]);
    }
    {
        const float4* s4 = (const float4*)hid;
        uint2* d4 = (uint2*)hidH;
        for (size_t i = g; i < (size_t)NB * 256 / 4; i += stride) d4[i] = cvt4(s4[i]);
    }
    for (int i = g; i < 256 * 128; i += stride) wencH[i] = f2h(Wenc[i]);
    for (int i = g; i < 64 * 256; i += stride) {
        wqkvH[i]         = f2h(Wq[i]);
        wqkvH[16384 + i] = f2h(Wk[i]);
        wqkvH[32768 + i] = f2h(Wv[i]);
    }
    for (int i = g; i < 1024 * 448; i += stride) {
        int n = i / 448, k = i - n * 448;
        int h = n >> 2, gg = n & 3, r = gg * 256 + h;
        float v = (k < 192) ? Wih[(size_t)r * 192 + k] : Whh[(size_t)r * 256 + (k - 192)];
        wcatH[i] = f2h(v);
    }
    for (int i = g; i < 32 * 256; i += stride) wdecH[i] = f2h(Wdec[i]);
}

// ---------------- launch ----------------------------------------------------
extern "C" void kernel_launch(void* const* d_in, const int* in_sizes, int n_in,
                              void* d_out, int out_size)
{
    const float* mo    = (const float*)d_in[0];
    const float* hid   = (const float*)d_in[1];
    const float* cell  = (const float*)d_in[2];
    const float* Wenc  = (const float*)d_in[3];
    const float* benc  = (const float*)d_in[4];
    const float* Wq    = (const float*)d_in[5];
    const float* Wk    = (const float*)d_in[6];
    const float* Wv    = (const float*)d_in[7];
    const float* bv    = (const float*)d_in[8];
    const float* Wih   = (const float*)d_in[9];
    const float* Whh   = (const float*)d_in[10];
    const float* bih   = (const float*)d_in[11];
    const float* bhh   = (const float*)d_in[12];
    const float* Wdec  = (const float*)d_in[13];
    const float* bdec  = (const float*)d_in[14];

    float* out   = (float*)d_out;
    float* m_act = out;
    float* h_out = out + (size_t)NB * NA_DIM;
    float* c_out = h_out + (size_t)NB * H_DIM;

    uint16_t *moH, *hidH, *xH, *eH, *hH, *wencH, *wqkvH, *wcatH, *wdecH;
    cudaGetSymbolAddress((void**)&moH,   g_moH);
    cudaGetSymbolAddress((void**)&hidH,  g_hidH);
    cudaGetSymbolAddress((void**)&xH,    g_xH);
    cudaGetSymbolAddress((void**)&eH,    g_eH);
    cudaGetSymbolAddress((void**)&hH,    g_hH);
    cudaGetSymbolAddress((void**)&wencH, g_wencH);
    cudaGetSymbolAddress((void**)&wqkvH, g_wqkvH);
    cudaGetSymbolAddress((void**)&wcatH, g_wcatH);
    cudaGetSymbolAddress((void**)&wdecH, g_wdecH);

    cudaFuncSetAttribute(gemm_f16<0>, cudaFuncAttributeMaxDynamicSharedMemorySize, 61440);
    cudaFuncSetAttribute(gemm_f16<3>, cudaFuncAttributeMaxDynamicSharedMemorySize, 38400);
    cudaFuncSetAttribute(gates_kernel, cudaFuncAttributeMaxDynamicSharedMemorySize,
                         G_S * G_STAGE);                 // 20480
    cudaFuncSetAttribute(qkv_attn_kernel, cudaFuncAttributeMaxDynamicSharedMemorySize, QK_SMEM);

    // 0) pack + convert to fp16
    pack_kernel<<<2048, 256>>>(mo, hid, Wenc, Wq, Wk, Wv, Wih, Whh, Wdec,
                               moH, hidH, wencH, wqkvH, wcatH, wdecH);
    // 1) encoder
    {
        GP p{}; p.A = moH; p.B0 = wencH; p.bias0 = benc; p.outH = xH;
        gemm_f16<0><<<dim3(2, 1024), 256, 61440>>>(p);
    }
    // 2) fused qkv + attention -> eH
    qkv_attn_kernel<<<1024, 256, QK_SMEM>>>(xH, wqkvH, bv, eH);
    // 3) gates GEMM (64x64 tiles, 8 CTAs/SM, S=2) + fused LSTM
    gates_kernel<<<dim3(16, 2048), 128, G_S * G_STAGE>>>(
        moH, eH, hidH, wcatH, bih, bhh, cell, h_out, c_out, hH);
    // 4) decoder
    {
        GP p{}; p.A = hH; p.B0 = wdecH; p.bias0 = bdec; p.out0 = m_act;
        gemm_f16<3><<<dim3(1, 1024), 256, 38400>>>(p);
    }
}

// round 16
// speedup vs baseline: 1.0678x; 1.0678x over previous
#include <cuda_runtime.h>
#include <cuda_fp16.h>
#include <math.h>
#include <stdint.h>

// Problem constants
#define NBAT   16384
#define NMAST  8
#define NB     (NBAT * NMAST)   // 131072
#define IN_DIM 128
#define H_DIM  256
#define A_DIM  64
#define NA_DIM 32

// ---------------- scratch ----------------------------------------------------
__device__ uint16_t g_moH [(size_t)NB * IN_DIM];
__device__ uint16_t g_hidH[(size_t)NB * H_DIM];
__device__ uint16_t g_xH  [(size_t)NB * H_DIM];   // encoder out, fp16
__device__ uint16_t g_eH  [(size_t)NB * A_DIM];   // attention out, fp16
__device__ uint16_t g_hH  [(size_t)NB * H_DIM];   // h_out copy, fp16
__device__ uint16_t g_wencH[256 * 128];
__device__ uint16_t g_wqkvH[3 * 64 * 256];        // [192][256]: q|k|v rows
__device__ uint16_t g_wcatH[1024 * 448];          // gate-interleaved [h*4+g][448]
__device__ uint16_t g_wdecH[32 * 256];

// ---------------- helpers ----------------------------------------------------
__device__ __forceinline__ uint16_t f2h(float f) {
    return __half_as_ushort(__float2half_rn(f));
}
__device__ __forceinline__ void mma16(float* c, const uint32_t* a, const uint32_t* b) {
    asm volatile(
        "mma.sync.aligned.m16n8k16.row.col.f32.f16.f16.f32 "
        "{%0,%1,%2,%3},{%4,%5,%6,%7},{%8,%9},{%0,%1,%2,%3};\n"
        : "+f"(c[0]), "+f"(c[1]), "+f"(c[2]), "+f"(c[3])
        : "r"(a[0]), "r"(a[1]), "r"(a[2]), "r"(a[3]), "r"(b[0]), "r"(b[1]));
}
__device__ __forceinline__ void ldsm4(uint32_t* r, uint32_t saddr) {
    asm volatile("ldmatrix.sync.aligned.m8n8.x4.shared.b16 {%0,%1,%2,%3}, [%4];"
        : "=r"(r[0]), "=r"(r[1]), "=r"(r[2]), "=r"(r[3]) : "r"(saddr));
}
__device__ __forceinline__ void cp16(uint32_t dst, const void* src) {
    asm volatile("cp.async.cg.shared.global [%0], [%1], 16;\n" :: "r"(dst), "l"(src));
}
__device__ __forceinline__ void cp_commit() {
    asm volatile("cp.async.commit_group;\n");
}
template<int N>
__device__ __forceinline__ void cp_wait() {
    asm volatile("cp.async.wait_group %0;\n" :: "n"(N));
}
__device__ __forceinline__ float sigf(float x) { return 1.f / (1.f + expf(-x)); }

struct GP {
    const uint16_t *A;
    const uint16_t *B0;
    const float *bias0;
    float *out0;
    uint16_t *outH;
};

// ============================================================================
// fused QKV GEMM + masked self-attention (unchanged)
// ============================================================================
#define QK_ITERS 8
#define QK_S 3
#define QK_ASTAGE 10240u
#define QK_BSTAGE 15360u
#define QK_SMEM 104448u

__global__ void __launch_bounds__(256, 1) qkv_attn_kernel(
    const uint16_t* __restrict__ xH, const uint16_t* __restrict__ wqkvH,
    const float* __restrict__ bv, uint16_t* __restrict__ eH)
{
    extern __shared__ uint32_t smem_u[];
    const uint32_t As_sh = (uint32_t)__cvta_generic_to_shared(smem_u);
    const uint32_t Bs_sh = As_sh + QK_S * QK_ASTAGE;

    const int tid  = threadIdx.x;
    const int lane = tid & 31, warp = tid >> 5;
    const int wr = warp >> 1, wc = warp & 1;
    const int qq = lane & 3, rr = lane >> 2;
    const int m0 = blockIdx.x * 128;

    const int a_r = lane & 15, a_h = lane >> 4;
    const int b_g = lane >> 3, b_rl = lane & 7;
    const int b_row = (b_g >> 1) * 8 + b_rl;
    const int b_k16 = (b_g & 1) * 16;

    auto issue = [&](int it, int s) {
        uint32_t Ast = As_sh + (uint32_t)s * QK_ASTAGE;
        uint32_t Bst = Bs_sh + (uint32_t)s * QK_BSTAGE;
        #pragma unroll
        for (int t5 = 0; t5 < 5; ++t5) {
            int t = tid + t5 * 256;
            if (t < 512) {
                int row = t >> 2, seg = t & 3;
                cp16(Ast + (uint32_t)(row * 80 + seg * 16),
                     xH + (size_t)(m0 + row) * 256 + it * 32 + seg * 8);
            } else {
                int u = t - 512;
                int row = u >> 2, seg = u & 3;
                cp16(Bst + (uint32_t)(row * 80 + seg * 16),
                     wqkvH + (size_t)row * 256 + it * 32 + seg * 8);
            }
        }
    };

    float acc[2][12][4];
    #pragma unroll
    for (int i = 0; i < 2; i++)
        #pragma unroll
        for (int j = 0; j < 12; j++)
            #pragma unroll
            for (int t = 0; t < 4; t++) acc[i][j][t] = 0.f;

    issue(0, 0); cp_commit();
    issue(1, 1); cp_commit();

    #pragma unroll
    for (int it = 0; it < QK_ITERS; ++it) {
        const int s  = it % QK_S;
        const int s2 = (it + 2) % QK_S;
        cp_wait<1>();
        __syncthreads();
        if (it + 2 < QK_ITERS) issue(it + 2, s2);
        cp_commit();

        const uint32_t Ab = As_sh + (uint32_t)s * QK_ASTAGE;
        const uint32_t Bb = Bs_sh + (uint32_t)s * QK_BSTAGE;
        #pragma unroll
        for (int ph = 0; ph < 2; ++ph) {
            uint32_t af[2][4], bf[12][2];
            #pragma unroll
            for (int mi = 0; mi < 2; ++mi)
                ldsm4(af[mi], Ab + (uint32_t)((wr * 32 + mi * 16 + a_r) * 80
                                              + ph * 32 + a_h * 16));
            #pragma unroll
            for (int pi = 0; pi < 6; ++pi)
                ldsm4(&bf[2 * pi][0], Bb + (uint32_t)((wc * 96 + pi * 16 + b_row) * 80
                                                      + ph * 32 + b_k16));
            #pragma unroll
            for (int mi = 0; mi < 2; ++mi)
                #pragma unroll
                for (int ni = 0; ni < 12; ++ni)
                    mma16(acc[mi][ni], af[mi], bf[ni]);
        }
    }
    cp_wait<0>();
    __syncthreads();

    float* sq = (float*)smem_u;
    float* sk = sq + 128 * 68;
    float* sv = sk + 128 * 68;
    #pragma unroll
    for (int mi = 0; mi < 2; ++mi)
        #pragma unroll
        for (int ni = 0; ni < 12; ++ni) {
            int col = wc * 96 + ni * 8 + qq * 2;
            int mat = col >> 6, loc = col & 63;
            int m = wr * 32 + mi * 16 + rr;
            float v0 = acc[mi][ni][0], v1 = acc[mi][ni][1];
            float v2 = acc[mi][ni][2], v3 = acc[mi][ni][3];
            float* dst = (mat == 0) ? sq : (mat == 1) ? sk : sv;
            if (mat == 2) {
                float b0 = bv[loc], b1 = bv[loc + 1];
                v0 = fmaxf(v0 + b0, 0.f); v1 = fmaxf(v1 + b1, 0.f);
                v2 = fmaxf(v2 + b0, 0.f); v3 = fmaxf(v3 + b1, 0.f);
            }
            dst[m * 68 + loc]           = v0;
            dst[m * 68 + loc + 1]       = v1;
            dst[(m + 8) * 68 + loc]     = v2;
            dst[(m + 8) * 68 + loc + 1] = v3;
        }
    __syncthreads();

    const int j  = lane & 7;
    const int i0 = lane >> 3;
    const int i1 = i0 + 4;
    const unsigned fm = 0xffffffffu;
    #pragma unroll
    for (int gi = 0; gi < 2; ++gi) {
        const int r0 = (warp * 2 + gi) * 8;
        float s0 = 0.f, s1 = 0.f;
        #pragma unroll
        for (int a = 0; a < A_DIM; a++) {
            float kv = sk[(r0 + j) * 68 + a];
            s0 = fmaf(sq[(r0 + i0) * 68 + a], kv, s0);
            s1 = fmaf(sq[(r0 + i1) * 68 + a], kv, s1);
        }
        s0 *= 0.125f; s1 *= 0.125f;
        if (i0 == j) s0 = -1e9f;
        if (i1 == j) s1 = -1e9f;

        float mm0 = s0, mm1 = s1;
        #pragma unroll
        for (int o = 4; o >= 1; o >>= 1) {
            mm0 = fmaxf(mm0, __shfl_xor_sync(fm, mm0, o));
            mm1 = fmaxf(mm1, __shfl_xor_sync(fm, mm1, o));
        }
        float e0 = expf(s0 - mm0), e1 = expf(s1 - mm1);
        float z0 = e0, z1 = e1;
        #pragma unroll
        for (int o = 4; o >= 1; o >>= 1) {
            z0 += __shfl_xor_sync(fm, z0, o);
            z1 += __shfl_xor_sync(fm, z1, o);
        }
        float w0 = e0 / z0, w1 = e1 / z1;

        float av[8][2] = {};
        #pragma unroll
        for (int i = 0; i < 8; i++) {
            #pragma unroll
            for (int jj = 0; jj < 8; jj++) {
                float wij = __shfl_sync(fm, (i < 4) ? w0 : w1, ((i & 3) << 3) + jj);
                av[i][0] = fmaf(wij, sv[(r0 + jj) * 68 + lane],      av[i][0]);
                av[i][1] = fmaf(wij, sv[(r0 + jj) * 68 + lane + 32], av[i][1]);
            }
        }
        #pragma unroll
        for (int i = 0; i < 8; i++) {
            uint16_t* er = eH + (size_t)(m0 + r0 + i) * 64;
            er[lane]      = f2h(av[i][0]);
            er[lane + 32] = f2h(av[i][1]);
        }
    }
}

// ============================================================================
// gates: 64x64 CTA tile, 128 threads, 7 CTAs/SM, S=3 (R14 config, proven)
// ============================================================================
#define G_ITERS 14
#define G_S 3
#define G_ROW 80u
#define G_STAGE (128u * G_ROW)     // 10240 B

__global__ void __launch_bounds__(128, 7) gates_kernel(
    const uint16_t* __restrict__ moH, const uint16_t* __restrict__ eH,
    const uint16_t* __restrict__ hidH, const uint16_t* __restrict__ wcatH,
    const float* __restrict__ bih, const float* __restrict__ bhh,
    const float* __restrict__ cell,
    float* __restrict__ h_out, float* __restrict__ c_out,
    uint16_t* __restrict__ hH)
{
    extern __shared__ uint32_t smem_u[];
    const uint32_t base_sh = (uint32_t)__cvta_generic_to_shared(smem_u);

    const int tid  = threadIdx.x;
    const int lane = tid & 31, warp = tid >> 5;
    const int wr = warp >> 1, wc = warp & 1;      // 2 m-groups x 2 n-groups
    const int q  = lane & 3,  rr = lane >> 2;
    const int m0 = blockIdx.y * 64;
    const int bx = blockIdx.x;                    // 16 n-tiles (64 cols = 16 h)

    const int a_r = lane & 15, a_h = lane >> 4;
    const int b_g = lane >> 3, b_rl = lane & 7;
    const int b_row = (b_g >> 1) * 8 + b_rl;
    const int b_k16 = (b_g & 1) * 16;

    // load tasks: A rows 0..63 (2 per thread-round), B rows 64..127
    const int aRow0 = tid >> 2,         aSeg0 = tid & 3;
    const int aRow1 = (tid + 128) >> 2, aSeg1 = (tid + 128) & 3;
    const uint32_t aOff0 = (uint32_t)aRow0 * G_ROW + (uint32_t)aSeg0 * 16;
    const uint32_t aOff1 = (uint32_t)aRow1 * G_ROW + (uint32_t)aSeg1 * 16;
    const uint16_t* bSrc[2];
    uint32_t bOff[2];
    #pragma unroll
    for (int r = 0; r < 2; ++r) {
        int idx = tid + 256 + r * 128;            // 256..511
        int row = idx >> 2, seg = idx & 3;        // rows 64..127
        bOff[r] = (uint32_t)row * G_ROW + (uint32_t)seg * 16;
        bSrc[r] = wcatH + (size_t)(bx * 64 + row - 64) * 448 + seg * 8;
    }

    auto issue = [&](int it, int s) {
        uint32_t st = base_sh + (uint32_t)s * G_STAGE;
        const uint16_t *s0, *s1;
        if (it < 4)      { s0 = moH  + (size_t)(m0 + aRow0) * 128 + it * 32 + aSeg0 * 8;
                           s1 = moH  + (size_t)(m0 + aRow1) * 128 + it * 32 + aSeg1 * 8; }
        else if (it < 6) { s0 = eH   + (size_t)(m0 + aRow0) * 64 + (it - 4) * 32 + aSeg0 * 8;
                           s1 = eH   + (size_t)(m0 + aRow1) * 64 + (it - 4) * 32 + aSeg1 * 8; }
        else             { s0 = hidH + (size_t)(m0 + aRow0) * 256 + (it - 6) * 32 + aSeg0 * 8;
                           s1 = hidH + (size_t)(m0 + aRow1) * 256 + (it - 6) * 32 + aSeg1 * 8; }
        cp16(st + aOff0, s0);
        cp16(st + aOff1, s1);
        cp16(st + bOff[0], bSrc[0] + it * 32);
        cp16(st + bOff[1], bSrc[1] + it * 32);
    };

    float acc[2][4][4];
    #pragma unroll
    for (int i = 0; i < 2; i++)
        #pragma unroll
        for (int j = 0; j < 4; j++)
            #pragma unroll
            for (int t = 0; t < 4; t++) acc[i][j][t] = 0.f;

    issue(0, 0); cp_commit();
    issue(1, 1); cp_commit();

    #pragma unroll
    for (int it = 0; it < G_ITERS; ++it) {
        const int s  = it % G_S;
        const int s2 = (it + 2) % G_S;
        cp_wait<1>();
        __syncthreads();
        if (it + 2 < G_ITERS) issue(it + 2, s2);
        cp_commit();

        const uint32_t St = base_sh + (uint32_t)s * G_STAGE;
        #pragma unroll
        for (int ph = 0; ph < 2; ++ph) {
            uint32_t af[2][4], bf[4][2];
            #pragma unroll
            for (int mi = 0; mi < 2; ++mi)
                ldsm4(af[mi], St + (uint32_t)((wr * 32 + mi * 16 + a_r) * G_ROW
                                              + ph * 32 + a_h * 16));
            #pragma unroll
            for (int pi = 0; pi < 2; ++pi)
                ldsm4(&bf[2 * pi][0], St + (uint32_t)((64 + wc * 32 + pi * 16 + b_row) * G_ROW
                                                      + ph * 32 + b_k16));
            #pragma unroll
            for (int mi = 0; mi < 2; ++mi)
                #pragma unroll
                for (int ni = 0; ni < 4; ++ni)
                    mma16(acc[mi][ni], af[mi], bf[ni]);
        }
    }
    cp_wait<0>();
    __syncthreads();

    // ---- fused LSTM epilogue (64 rows x 16 h per CTA) ----
    float* smc = (float*)smem_u;            // cell tile [64][17]
    float* smr = smc + 64 * 17;             // h tile   [64][17]
    const int h0 = bx * 16;
    for (int i = tid; i < 1024; i += 128) {
        int m = i >> 4, h = i & 15;
        smc[m * 17 + h] = cell[(size_t)(m0 + m) * 256 + h0 + h];
    }
    __syncthreads();

    const bool even = (q & 1) == 0;
    #pragma unroll
    for (int ni = 0; ni < 4; ++ni) {
        int nb = wc * 32 + ni * 8;
        int h_loc = (nb >> 2) + (q >> 1);        // 0..15
        int hg = h0 + h_loc;
        int g0 = (q & 1) * 2;
        float bb0 = bih[g0 * 256 + hg] + bhh[g0 * 256 + hg];
        float bb1 = bih[(g0 + 1) * 256 + hg] + bhh[(g0 + 1) * 256 + hg];
        #pragma unroll
        for (int mi = 0; mi < 2; ++mi) {
            float c0 = acc[mi][ni][0] + bb0, c1 = acc[mi][ni][1] + bb1;
            float c2 = acc[mi][ni][2] + bb0, c3 = acc[mi][ni][3] + bb1;
            float p0 = __shfl_xor_sync(~0u, c0, 1);
            float p1 = __shfl_xor_sync(~0u, c1, 1);
            float p2 = __shfl_xor_sync(~0u, c2, 1);
            float p3 = __shfl_xor_sync(~0u, c3, 1);
            if (even) {
                int ml = wr * 32 + mi * 16 + rr;
                float cp0 = smc[ml * 17 + h_loc];
                float cp1 = smc[(ml + 8) * 17 + h_loc];
                float cn0 = sigf(c1) * cp0 + sigf(c0) * tanhf(p0);
                float hn0 = sigf(p1) * tanhf(cn0);
                float cn1 = sigf(c3) * cp1 + sigf(c2) * tanhf(p2);
                float hn1 = sigf(p3) * tanhf(cn1);
                acc[mi][ni][0] = hn0; acc[mi][ni][1] = cn0;
                acc[mi][ni][2] = hn1; acc[mi][ni][3] = cn1;
            }
        }
    }
    __syncthreads();
    #pragma unroll
    for (int ni = 0; ni < 4; ++ni) {
        int nb = wc * 32 + ni * 8;
        int h_loc = (nb >> 2) + (q >> 1);
        #pragma unroll
        for (int mi = 0; mi < 2; ++mi) {
            if (even) {
                int ml = wr * 32 + mi * 16 + rr;
                smr[ml * 17 + h_loc]       = acc[mi][ni][0];
                smc[ml * 17 + h_loc]       = acc[mi][ni][1];
                smr[(ml + 8) * 17 + h_loc] = acc[mi][ni][2];
                smc[(ml + 8) * 17 + h_loc] = acc[mi][ni][3];
            }
        }
    }
    __syncthreads();
    for (int i = tid; i < 1024; i += 128) {
        int m = i >> 4, h = i & 15;
        size_t off = (size_t)(m0 + m) * 256 + h0 + h;
        float hv = smr[m * 17 + h];
        h_out[off] = hv;
        c_out[off] = smc[m * 17 + h];
        hH[off]    = f2h(hv);
    }
}

// ============================================================================
// GEMM template: MODE 0 encoder (BN=128), MODE 3 decoder (BN=32)
// ============================================================================
template<int MODE>
__global__ void __launch_bounds__(256, 2) gemm_f16(GP p) {
    constexpr int BN = (MODE == 3) ? 32 : 128;
    constexpr int WC = (MODE == 3) ? 1  : 4;
    constexpr int WR = 8 / WC;
    constexpr int MT = 8 / WR;
    constexpr int NT = 4;
    constexpr int K  = (MODE == 0) ? 128 : 256;
    constexpr int ITERS = K / 32;
    constexpr int WTM = MT * 16;
    constexpr int S   = 3;
    constexpr int AK  = (MODE == 0) ? 128 : 256;
    constexpr int BKH = K;
    constexpr uint32_t ASTAGE_B = 128 * 80;
    constexpr uint32_t BSTAGE_B = BN * 80;

    extern __shared__ uint32_t smem_u[];
    const uint32_t As_sh = (uint32_t)__cvta_generic_to_shared(smem_u);
    const uint32_t Bs_sh = As_sh + S * ASTAGE_B;

    const int tid  = threadIdx.x;
    const int lane = tid & 31, warp = tid >> 5;
    const int wr = warp / WC, wc = warp % WC;
    const int q  = lane & 3,  rr = lane >> 2;
    const int m0 = blockIdx.y * 128;
    const int bx = blockIdx.x;

    const int arow = tid >> 2;
    const int aseg = tid & 3;
    const uint32_t tOff = (uint32_t)(arow * 80 + aseg * 16);

    const uint16_t* pA = p.A + (size_t)(m0 + arow) * AK + aseg * 8;
    const uint16_t* pB;
    if constexpr (MODE == 0) pB = p.B0 + (size_t)(bx * 128 + arow) * 128 + aseg * 8;
    else                     pB = p.B0 + (size_t)arow * 256 + aseg * 8;

    auto issue = [&](int it, int s) {
        uint32_t ad = As_sh + (uint32_t)s * ASTAGE_B + tOff;
        uint32_t bd = Bs_sh + (uint32_t)s * BSTAGE_B + tOff;
        const uint16_t* a0 = pA + it * 32;
        cp16(ad, a0);
        cp16(ad + 64 * 80, a0 + (size_t)64 * AK);
        if constexpr (BN == 128) {
            cp16(bd, pB + it * 32);
            cp16(bd + 64 * 80, pB + (size_t)64 * BKH + it * 32);
        } else {
            if (tid < 128) cp16(bd, pB + it * 32);
        }
    };

    float acc[MT][NT][4];
    #pragma unroll
    for (int i = 0; i < MT; i++)
        #pragma unroll
        for (int j = 0; j < NT; j++)
            #pragma unroll
            for (int t = 0; t < 4; t++) acc[i][j][t] = 0.f;

    const int a_r = lane & 15, a_h = lane >> 4;
    const int b_g = lane >> 3, b_rl = lane & 7;
    const int b_row = (b_g >> 1) * 8 + b_rl;
    const int b_k16 = (b_g & 1) * 16;

    issue(0, 0); cp_commit();
    issue(1, 1); cp_commit();

    #pragma unroll
    for (int it = 0; it < ITERS; ++it) {
        const int s  = it % S;
        const int s2 = (it + 2) % S;
        cp_wait<1>();
        __syncthreads();
        if (it + 2 < ITERS) issue(it + 2, s2);
        cp_commit();

        const uint32_t Ab = As_sh + (uint32_t)s * ASTAGE_B;
        const uint32_t Bb = Bs_sh + (uint32_t)s * BSTAGE_B;
        #pragma unroll
        for (int ph = 0; ph < 2; ++ph) {
            uint32_t af[MT][4], bf[NT][2];
            #pragma unroll
            for (int mi = 0; mi < MT; ++mi)
                ldsm4(af[mi], Ab + (uint32_t)((wr * WTM + mi * 16 + a_r) * 80
                                              + ph * 32 + a_h * 16));
            #pragma unroll
            for (int pi = 0; pi < NT / 2; ++pi)
                ldsm4(&bf[2 * pi][0], Bb + (uint32_t)((wc * 32 + pi * 16 + b_row) * 80
                                                      + ph * 32 + b_k16));
            #pragma unroll
            for (int mi = 0; mi < MT; ++mi)
                #pragma unroll
                for (int ni = 0; ni < NT; ++ni)
                    mma16(acc[mi][ni], af[mi], bf[ni]);
        }
    }
    cp_wait<0>();
    __syncthreads();

    if constexpr (MODE == 0) {
        #pragma unroll
        for (int mi = 0; mi < MT; ++mi)
            #pragma unroll
            for (int ni = 0; ni < NT; ++ni) {
                int n = bx * 128 + wc * 32 + ni * 8 + q * 2;
                int m = m0 + wr * WTM + mi * 16 + rr;
                float b0v = p.bias0[n], b1v = p.bias0[n + 1];
                __half2 h0 = __floats2half2_rn(fmaxf(acc[mi][ni][0] + b0v, 0.f),
                                               fmaxf(acc[mi][ni][1] + b1v, 0.f));
                __half2 h1 = __floats2half2_rn(fmaxf(acc[mi][ni][2] + b0v, 0.f),
                                               fmaxf(acc[mi][ni][3] + b1v, 0.f));
                *(__half2*)(p.outH + (size_t)m * 256 + n) = h0;
                *(__half2*)(p.outH + (size_t)(m + 8) * 256 + n) = h1;
            }
    } else {
        #pragma unroll
        for (int mi = 0; mi < MT; ++mi)
            #pragma unroll
            for (int ni = 0; ni < NT; ++ni) {
                int n = ni * 8 + q * 2;
                int m = m0 + wr * WTM + mi * 16 + rr;
                float b0v = p.bias0[n], b1v = p.bias0[n + 1];
                *(float2*)(p.out0 + (size_t)m * 32 + n) =
                    make_float2(acc[mi][ni][0] + b0v, acc[mi][ni][1] + b1v);
                *(float2*)(p.out0 + (size_t)(m + 8) * 32 + n) =
                    make_float2(acc[mi][ni][2] + b0v, acc[mi][ni][3] + b1v);
            }
    }
}

// ---------------- pack prologue: split main vs hid ---------------------------
__global__ void pack_main_kernel(const float* __restrict__ mo,
                                 const float* __restrict__ Wenc,
                                 const float* __restrict__ Wq, const float* __restrict__ Wk,
                                 const float* __restrict__ Wv,
                                 const float* __restrict__ Wih, const float* __restrict__ Whh,
                                 const float* __restrict__ Wdec,
                                 uint16_t* __restrict__ moH,
                                 uint16_t* __restrict__ wencH, uint16_t* __restrict__ wqkvH,
                                 uint16_t* __restrict__ wcatH, uint16_t* __restrict__ wdecH)
{
    const int stride = gridDim.x * blockDim.x;
    const int g = blockIdx.x * blockDim.x + threadIdx.x;
    auto cvt4 = [](float4 v) -> uint2 {
        __half2 h01 = __floats2half2_rn(v.x, v.y);
        __half2 h23 = __floats2half2_rn(v.z, v.w);
        return make_uint2(*(uint32_t*)&h01, *(uint32_t*)&h23);
    };
    {
        const float4* s4 = (const float4*)mo;
        uint2* d4 = (uint2*)moH;
        for (size_t i = g; i < (size_t)NB * 128 / 4; i += stride) d4[i] = cvt4(s4[i]);
    }
    for (int i = g; i < 256 * 128; i += stride) wencH[i] = f2h(Wenc[i]);
    for (int i = g; i < 64 * 256; i += stride) {
        wqkvH[i]         = f2h(Wq[i]);
        wqkvH[16384 + i] = f2h(Wk[i]);
        wqkvH[32768 + i] = f2h(Wv[i]);
    }
    for (int i = g; i < 1024 * 448; i += stride) {
        int n = i / 448, k = i - n * 448;
        int h = n >> 2, gg = n & 3, r = gg * 256 + h;
        float v = (k < 192) ? Wih[(size_t)r * 192 + k] : Whh[(size_t)r * 256 + (k - 192)];
        wcatH[i] = f2h(v);
    }
    for (int i = g; i < 32 * 256; i += stride) wdecH[i] = f2h(Wdec[i]);
}

__global__ void pack_hid_kernel(const float* __restrict__ hid,
                                uint16_t* __restrict__ hidH)
{
    const int stride = gridDim.x * blockDim.x;
    const int g = blockIdx.x * blockDim.x + threadIdx.x;
    const float4* s4 = (const float4*)hid;
    uint2* d4 = (uint2*)hidH;
    for (size_t i = g; i < (size_t)NB * 256 / 4; i += stride) {
        float4 v = s4[i];
        __half2 h01 = __floats2half2_rn(v.x, v.y);
        __half2 h23 = __floats2half2_rn(v.z, v.w);
        d4[i] = make_uint2(*(uint32_t*)&h01, *(uint32_t*)&h23);
    }
}

// ---------------- launch ----------------------------------------------------
extern "C" void kernel_launch(void* const* d_in, const int* in_sizes, int n_in,
                              void* d_out, int out_size)
{
    const float* mo    = (const float*)d_in[0];
    const float* hid   = (const float*)d_in[1];
    const float* cell  = (const float*)d_in[2];
    const float* Wenc  = (const float*)d_in[3];
    const float* benc  = (const float*)d_in[4];
    const float* Wq    = (const float*)d_in[5];
    const float* Wk    = (const float*)d_in[6];
    const float* Wv    = (const float*)d_in[7];
    const float* bv    = (const float*)d_in[8];
    const float* Wih   = (const float*)d_in[9];
    const float* Whh   = (const float*)d_in[10];
    const float* bih   = (const float*)d_in[11];
    const float* bhh   = (const float*)d_in[12];
    const float* Wdec  = (const float*)d_in[13];
    const float* bdec  = (const float*)d_in[14];

    float* out   = (float*)d_out;
    float* m_act = out;
    float* h_out = out + (size_t)NB * NA_DIM;
    float* c_out = h_out + (size_t)NB * H_DIM;

    uint16_t *moH, *hidH, *xH, *eH, *hH, *wencH, *wqkvH, *wcatH, *wdecH;
    cudaGetSymbolAddress((void**)&moH,   g_moH);
    cudaGetSymbolAddress((void**)&hidH,  g_hidH);
    cudaGetSymbolAddress((void**)&xH,    g_xH);
    cudaGetSymbolAddress((void**)&eH,    g_eH);
    cudaGetSymbolAddress((void**)&hH,    g_hH);
    cudaGetSymbolAddress((void**)&wencH, g_wencH);
    cudaGetSymbolAddress((void**)&wqkvH, g_wqkvH);
    cudaGetSymbolAddress((void**)&wcatH, g_wcatH);
    cudaGetSymbolAddress((void**)&wdecH, g_wdecH);

    cudaFuncSetAttribute(gemm_f16<0>, cudaFuncAttributeMaxDynamicSharedMemorySize, 61440);
    cudaFuncSetAttribute(gemm_f16<3>, cudaFuncAttributeMaxDynamicSharedMemorySize, 38400);
    cudaFuncSetAttribute(gates_kernel, cudaFuncAttributeMaxDynamicSharedMemorySize,
                         G_S * G_STAGE);                 // 30720
    cudaFuncSetAttribute(qkv_attn_kernel, cudaFuncAttributeMaxDynamicSharedMemorySize, QK_SMEM);

    // side stream for hid packing (non-blocking: no implicit legacy sync)
    cudaStream_t s2;
    cudaStreamCreateWithFlags(&s2, cudaStreamNonBlocking);
    cudaEvent_t e_fork, e_join;
    cudaEventCreateWithFlags(&e_fork, cudaEventDisableTiming);
    cudaEventCreateWithFlags(&e_join, cudaEventDisableTiming);

    // fork: hid pack runs concurrently with pack_main/encoder/qkv
    cudaEventRecord(e_fork, 0);
    cudaStreamWaitEvent(s2, e_fork, 0);
    pack_hid_kernel<<<2048, 256, 0, s2>>>(hid, hidH);
    cudaEventRecord(e_join, s2);

    // 0) pack mo + weights (default stream)
    pack_main_kernel<<<2048, 256>>>(mo, Wenc, Wq, Wk, Wv, Wih, Whh, Wdec,
                                    moH, wencH, wqkvH, wcatH, wdecH);
    // 1) encoder
    {
        GP p{}; p.A = moH; p.B0 = wencH; p.bias0 = benc; p.outH = xH;
        gemm_f16<0><<<dim3(2, 1024), 256, 61440>>>(p);
    }
    // 2) fused qkv + attention -> eH
    qkv_attn_kernel<<<1024, 256, QK_SMEM>>>(xH, wqkvH, bv, eH);

    // join: gates needs hidH
    cudaStreamWaitEvent(0, e_join, 0);

    // 3) gates GEMM (64x64 tiles, 7 CTAs/SM, S=3) + fused LSTM
    gates_kernel<<<dim3(16, 2048), 128, G_S * G_STAGE>>>(
        moH, eH, hidH, wcatH, bih, bhh, cell, h_out, c_out, hH);
    // 4) decoder
    {
        GP p{}; p.A = hH; p.B0 = wdecH; p.bias0 = bdec; p.out0 = m_act;
        gemm_f16<3><<<dim3(1, 1024), 256, 38400>>>(p);
    }
}

// round 17
// speedup vs baseline: 1.0727x; 1.0046x over previous
#include <cuda_runtime.h>
#include <cuda_fp16.h>
#include <math.h>
#include <stdint.h>

// Problem constants
#define NBAT   16384
#define NMAST  8
#define NB     (NBAT * NMAST)   // 131072
#define IN_DIM 128
#define H_DIM  256
#define A_DIM  64
#define NA_DIM 32

// ---------------- scratch ----------------------------------------------------
__device__ uint16_t g_moH [(size_t)NB * IN_DIM];
__device__ uint16_t g_hidH[(size_t)NB * H_DIM];
__device__ uint16_t g_xH  [(size_t)NB * H_DIM];   // encoder out, fp16
__device__ uint16_t g_eH  [(size_t)NB * A_DIM];   // attention out, fp16
__device__ uint16_t g_hH  [(size_t)NB * H_DIM];   // h_out copy, fp16
__device__ uint16_t g_wencH[256 * 128];
__device__ uint16_t g_wqkvH[3 * 64 * 256];        // [192][256]: q|k|v rows
__device__ uint16_t g_wcatH[1024 * 448];          // gate-interleaved [h*4+g][448]
__device__ uint16_t g_wdecH[32 * 256];

// ---------------- helpers ----------------------------------------------------
__device__ __forceinline__ uint16_t f2h(float f) {
    return __half_as_ushort(__float2half_rn(f));
}
__device__ __forceinline__ void mma16(float* c, const uint32_t* a, const uint32_t* b) {
    asm volatile(
        "mma.sync.aligned.m16n8k16.row.col.f32.f16.f16.f32 "
        "{%0,%1,%2,%3},{%4,%5,%6,%7},{%8,%9},{%0,%1,%2,%3};\n"
        : "+f"(c[0]), "+f"(c[1]), "+f"(c[2]), "+f"(c[3])
        : "r"(a[0]), "r"(a[1]), "r"(a[2]), "r"(a[3]), "r"(b[0]), "r"(b[1]));
}
__device__ __forceinline__ void ldsm4(uint32_t* r, uint32_t saddr) {
    asm volatile("ldmatrix.sync.aligned.m8n8.x4.shared.b16 {%0,%1,%2,%3}, [%4];"
        : "=r"(r[0]), "=r"(r[1]), "=r"(r[2]), "=r"(r[3]) : "r"(saddr));
}
__device__ __forceinline__ void cp16(uint32_t dst, const void* src) {
    asm volatile("cp.async.cg.shared.global [%0], [%1], 16;\n" :: "r"(dst), "l"(src));
}
__device__ __forceinline__ void cp_commit() {
    asm volatile("cp.async.commit_group;\n");
}
template<int N>
__device__ __forceinline__ void cp_wait() {
    asm volatile("cp.async.wait_group %0;\n" :: "n"(N));
}
__device__ __forceinline__ float sigf(float x) { return 1.f / (1.f + expf(-x)); }

struct GP {
    const uint16_t *A;
    const uint16_t *B0;
    const float *bias0;
    float *out0;
    uint16_t *outH;
};

// ============================================================================
// fused QKV GEMM + masked self-attention — 64-row CTAs, 32x48 warp tiles,
// 2 CTAs/SM. Stage: rows 0-63 A(x), rows 64-255 B(wqkv). 80B stride.
// ============================================================================
#define QK_ITERS 8
#define QK_S 3
#define QK_STAGE 20480u            // 256 rows * 80B
#define QK_SMEM  (QK_S * QK_STAGE) // 61440

__global__ void __launch_bounds__(256, 2) qkv_attn_kernel(
    const uint16_t* __restrict__ xH, const uint16_t* __restrict__ wqkvH,
    const float* __restrict__ bv, uint16_t* __restrict__ eH)
{
    extern __shared__ uint32_t smem_u[];
    const uint32_t base_sh = (uint32_t)__cvta_generic_to_shared(smem_u);

    const int tid  = threadIdx.x;
    const int lane = tid & 31, warp = tid >> 5;
    const int wr = warp >> 2, wc = warp & 3;     // 2 m-groups x 4 n-groups
    const int qq = lane & 3, rr = lane >> 2;
    const int m0 = blockIdx.x * 64;

    const int a_r = lane & 15, a_h = lane >> 4;
    const int b_g = lane >> 3, b_rl = lane & 7;
    const int b_row = (b_g >> 1) * 8 + b_rl;
    const int b_k16 = (b_g & 1) * 16;

    auto issue = [&](int it, int s) {
        uint32_t st = base_sh + (uint32_t)s * QK_STAGE;
        #pragma unroll
        for (int r = 0; r < 4; ++r) {
            int t = tid + r * 256;               // 0..1023
            if (t < 256) {
                int row = t >> 2, seg = t & 3;
                cp16(st + (uint32_t)(row * 80 + seg * 16),
                     xH + (size_t)(m0 + row) * 256 + it * 32 + seg * 8);
            } else {
                int u = t - 256;
                int row = u >> 2, seg = u & 3;   // row 0..191
                cp16(st + (uint32_t)((64 + row) * 80 + seg * 16),
                     wqkvH + (size_t)row * 256 + it * 32 + seg * 8);
            }
        }
    };

    float acc[2][6][4];
    #pragma unroll
    for (int i = 0; i < 2; i++)
        #pragma unroll
        for (int j = 0; j < 6; j++)
            #pragma unroll
            for (int t = 0; t < 4; t++) acc[i][j][t] = 0.f;

    issue(0, 0); cp_commit();
    issue(1, 1); cp_commit();

    #pragma unroll
    for (int it = 0; it < QK_ITERS; ++it) {
        const int s  = it % QK_S;
        const int s2 = (it + 2) % QK_S;
        cp_wait<1>();
        __syncthreads();
        if (it + 2 < QK_ITERS) issue(it + 2, s2);
        cp_commit();

        const uint32_t St = base_sh + (uint32_t)s * QK_STAGE;
        #pragma unroll
        for (int ph = 0; ph < 2; ++ph) {
            uint32_t af[2][4], bf[6][2];
            #pragma unroll
            for (int mi = 0; mi < 2; ++mi)
                ldsm4(af[mi], St + (uint32_t)((wr * 32 + mi * 16 + a_r) * 80
                                              + ph * 32 + a_h * 16));
            #pragma unroll
            for (int pi = 0; pi < 3; ++pi)
                ldsm4(&bf[2 * pi][0], St + (uint32_t)((64 + wc * 48 + pi * 16 + b_row) * 80
                                                      + ph * 32 + b_k16));
            #pragma unroll
            for (int mi = 0; mi < 2; ++mi)
                #pragma unroll
                for (int ni = 0; ni < 6; ++ni)
                    mma16(acc[mi][ni], af[mi], bf[ni]);
        }
    }
    cp_wait<0>();
    __syncthreads();

    // ---- stage q,k,v (fp32) into smem [64][68] each
    float* sq = (float*)smem_u;
    float* sk = sq + 64 * 68;
    float* sv = sk + 64 * 68;
    #pragma unroll
    for (int mi = 0; mi < 2; ++mi)
        #pragma unroll
        for (int ni = 0; ni < 6; ++ni) {
            int col = wc * 48 + ni * 8 + qq * 2;
            int mat = col >> 6, loc = col & 63;
            int m = wr * 32 + mi * 16 + rr;
            float v0 = acc[mi][ni][0], v1 = acc[mi][ni][1];
            float v2 = acc[mi][ni][2], v3 = acc[mi][ni][3];
            float* dst = (mat == 0) ? sq : (mat == 1) ? sk : sv;
            if (mat == 2) {
                float b0 = bv[loc], b1 = bv[loc + 1];
                v0 = fmaxf(v0 + b0, 0.f); v1 = fmaxf(v1 + b1, 0.f);
                v2 = fmaxf(v2 + b0, 0.f); v3 = fmaxf(v3 + b1, 0.f);
            }
            dst[m * 68 + loc]           = v0;
            dst[m * 68 + loc + 1]       = v1;
            dst[(m + 8) * 68 + loc]     = v2;
            dst[(m + 8) * 68 + loc + 1] = v3;
        }
    __syncthreads();

    // ---- attention: warp w handles group w (8 rows)
    const int j  = lane & 7;
    const int i0 = lane >> 3;
    const int i1 = i0 + 4;
    const unsigned fm = 0xffffffffu;
    const int r0 = warp * 8;
    float s0 = 0.f, s1 = 0.f;
    #pragma unroll
    for (int a = 0; a < A_DIM; a++) {
        float kv = sk[(r0 + j) * 68 + a];
        s0 = fmaf(sq[(r0 + i0) * 68 + a], kv, s0);
        s1 = fmaf(sq[(r0 + i1) * 68 + a], kv, s1);
    }
    s0 *= 0.125f; s1 *= 0.125f;
    if (i0 == j) s0 = -1e9f;
    if (i1 == j) s1 = -1e9f;

    float mm0 = s0, mm1 = s1;
    #pragma unroll
    for (int o = 4; o >= 1; o >>= 1) {
        mm0 = fmaxf(mm0, __shfl_xor_sync(fm, mm0, o));
        mm1 = fmaxf(mm1, __shfl_xor_sync(fm, mm1, o));
    }
    float e0 = expf(s0 - mm0), e1 = expf(s1 - mm1);
    float z0 = e0, z1 = e1;
    #pragma unroll
    for (int o = 4; o >= 1; o >>= 1) {
        z0 += __shfl_xor_sync(fm, z0, o);
        z1 += __shfl_xor_sync(fm, z1, o);
    }
    float w0 = e0 / z0, w1 = e1 / z1;

    float av[8][2] = {};
    #pragma unroll
    for (int i = 0; i < 8; i++) {
        #pragma unroll
        for (int jj = 0; jj < 8; jj++) {
            float wij = __shfl_sync(fm, (i < 4) ? w0 : w1, ((i & 3) << 3) + jj);
            av[i][0] = fmaf(wij, sv[(r0 + jj) * 68 + lane],      av[i][0]);
            av[i][1] = fmaf(wij, sv[(r0 + jj) * 68 + lane + 32], av[i][1]);
        }
    }
    #pragma unroll
    for (int i = 0; i < 8; i++) {
        uint16_t* er = eH + (size_t)(m0 + r0 + i) * 64;
        er[lane]      = f2h(av[i][0]);
        er[lane + 32] = f2h(av[i][1]);
    }
}

// ============================================================================
// gates: 64x64 CTA tile, 128 threads, 7 CTAs/SM, S=3 (R14 proven config)
// ============================================================================
#define G_ITERS 14
#define G_S 3
#define G_ROW 80u
#define G_STAGE (128u * G_ROW)     // 10240 B

__global__ void __launch_bounds__(128, 7) gates_kernel(
    const uint16_t* __restrict__ moH, const uint16_t* __restrict__ eH,
    const uint16_t* __restrict__ hidH, const uint16_t* __restrict__ wcatH,
    const float* __restrict__ bih, const float* __restrict__ bhh,
    const float* __restrict__ cell,
    float* __restrict__ h_out, float* __restrict__ c_out,
    uint16_t* __restrict__ hH)
{
    extern __shared__ uint32_t smem_u[];
    const uint32_t base_sh = (uint32_t)__cvta_generic_to_shared(smem_u);

    const int tid  = threadIdx.x;
    const int lane = tid & 31, warp = tid >> 5;
    const int wr = warp >> 1, wc = warp & 1;      // 2 m-groups x 2 n-groups
    const int q  = lane & 3,  rr = lane >> 2;
    const int m0 = blockIdx.y * 64;
    const int bx = blockIdx.x;                    // 16 n-tiles (64 cols = 16 h)

    const int a_r = lane & 15, a_h = lane >> 4;
    const int b_g = lane >> 3, b_rl = lane & 7;
    const int b_row = (b_g >> 1) * 8 + b_rl;
    const int b_k16 = (b_g & 1) * 16;

    const int aRow0 = tid >> 2,         aSeg0 = tid & 3;
    const int aRow1 = (tid + 128) >> 2, aSeg1 = (tid + 128) & 3;
    const uint32_t aOff0 = (uint32_t)aRow0 * G_ROW + (uint32_t)aSeg0 * 16;
    const uint32_t aOff1 = (uint32_t)aRow1 * G_ROW + (uint32_t)aSeg1 * 16;
    const uint16_t* bSrc[2];
    uint32_t bOff[2];
    #pragma unroll
    for (int r = 0; r < 2; ++r) {
        int idx = tid + 256 + r * 128;            // 256..511
        int row = idx >> 2, seg = idx & 3;        // rows 64..127
        bOff[r] = (uint32_t)row * G_ROW + (uint32_t)seg * 16;
        bSrc[r] = wcatH + (size_t)(bx * 64 + row - 64) * 448 + seg * 8;
    }

    auto issue = [&](int it, int s) {
        uint32_t st = base_sh + (uint32_t)s * G_STAGE;
        const uint16_t *s0, *s1;
        if (it < 4)      { s0 = moH  + (size_t)(m0 + aRow0) * 128 + it * 32 + aSeg0 * 8;
                           s1 = moH  + (size_t)(m0 + aRow1) * 128 + it * 32 + aSeg1 * 8; }
        else if (it < 6) { s0 = eH   + (size_t)(m0 + aRow0) * 64 + (it - 4) * 32 + aSeg0 * 8;
                           s1 = eH   + (size_t)(m0 + aRow1) * 64 + (it - 4) * 32 + aSeg1 * 8; }
        else             { s0 = hidH + (size_t)(m0 + aRow0) * 256 + (it - 6) * 32 + aSeg0 * 8;
                           s1 = hidH + (size_t)(m0 + aRow1) * 256 + (it - 6) * 32 + aSeg1 * 8; }
        cp16(st + aOff0, s0);
        cp16(st + aOff1, s1);
        cp16(st + bOff[0], bSrc[0] + it * 32);
        cp16(st + bOff[1], bSrc[1] + it * 32);
    };

    float acc[2][4][4];
    #pragma unroll
    for (int i = 0; i < 2; i++)
        #pragma unroll
        for (int j = 0; j < 4; j++)
            #pragma unroll
            for (int t = 0; t < 4; t++) acc[i][j][t] = 0.f;

    issue(0, 0); cp_commit();
    issue(1, 1); cp_commit();

    #pragma unroll
    for (int it = 0; it < G_ITERS; ++it) {
        const int s  = it % G_S;
        const int s2 = (it + 2) % G_S;
        cp_wait<1>();
        __syncthreads();
        if (it + 2 < G_ITERS) issue(it + 2, s2);
        cp_commit();

        const uint32_t St = base_sh + (uint32_t)s * G_STAGE;
        #pragma unroll
        for (int ph = 0; ph < 2; ++ph) {
            uint32_t af[2][4], bf[4][2];
            #pragma unroll
            for (int mi = 0; mi < 2; ++mi)
                ldsm4(af[mi], St + (uint32_t)((wr * 32 + mi * 16 + a_r) * G_ROW
                                              + ph * 32 + a_h * 16));
            #pragma unroll
            for (int pi = 0; pi < 2; ++pi)
                ldsm4(&bf[2 * pi][0], St + (uint32_t)((64 + wc * 32 + pi * 16 + b_row) * G_ROW
                                                      + ph * 32 + b_k16));
            #pragma unroll
            for (int mi = 0; mi < 2; ++mi)
                #pragma unroll
                for (int ni = 0; ni < 4; ++ni)
                    mma16(acc[mi][ni], af[mi], bf[ni]);
        }
    }
    cp_wait<0>();
    __syncthreads();

    // ---- fused LSTM epilogue (64 rows x 16 h per CTA) ----
    float* smc = (float*)smem_u;            // cell tile [64][17]
    float* smr = smc + 64 * 17;             // h tile   [64][17]
    const int h0 = bx * 16;
    for (int i = tid; i < 1024; i += 128) {
        int m = i >> 4, h = i & 15;
        smc[m * 17 + h] = cell[(size_t)(m0 + m) * 256 + h0 + h];
    }
    __syncthreads();

    const bool even = (q & 1) == 0;
    #pragma unroll
    for (int ni = 0; ni < 4; ++ni) {
        int nb = wc * 32 + ni * 8;
        int h_loc = (nb >> 2) + (q >> 1);        // 0..15
        int hg = h0 + h_loc;
        int g0 = (q & 1) * 2;
        float bb0 = bih[g0 * 256 + hg] + bhh[g0 * 256 + hg];
        float bb1 = bih[(g0 + 1) * 256 + hg] + bhh[(g0 + 1) * 256 + hg];
        #pragma unroll
        for (int mi = 0; mi < 2; ++mi) {
            float c0 = acc[mi][ni][0] + bb0, c1 = acc[mi][ni][1] + bb1;
            float c2 = acc[mi][ni][2] + bb0, c3 = acc[mi][ni][3] + bb1;
            float p0 = __shfl_xor_sync(~0u, c0, 1);
            float p1 = __shfl_xor_sync(~0u, c1, 1);
            float p2 = __shfl_xor_sync(~0u, c2, 1);
            float p3 = __shfl_xor_sync(~0u, c3, 1);
            if (even) {
                int ml = wr * 32 + mi * 16 + rr;
                float cp0 = smc[ml * 17 + h_loc];
                float cp1 = smc[(ml + 8) * 17 + h_loc];
                float cn0 = sigf(c1) * cp0 + sigf(c0) * tanhf(p0);
                float hn0 = sigf(p1) * tanhf(cn0);
                float cn1 = sigf(c3) * cp1 + sigf(c2) * tanhf(p2);
                float hn1 = sigf(p3) * tanhf(cn1);
                acc[mi][ni][0] = hn0; acc[mi][ni][1] = cn0;
                acc[mi][ni][2] = hn1; acc[mi][ni][3] = cn1;
            }
        }
    }
    __syncthreads();
    #pragma unroll
    for (int ni = 0; ni < 4; ++ni) {
        int nb = wc * 32 + ni * 8;
        int h_loc = (nb >> 2) + (q >> 1);
        #pragma unroll
        for (int mi = 0; mi < 2; ++mi) {
            if (even) {
                int ml = wr * 32 + mi * 16 + rr;
                smr[ml * 17 + h_loc]       = acc[mi][ni][0];
                smc[ml * 17 + h_loc]       = acc[mi][ni][1];
                smr[(ml + 8) * 17 + h_loc] = acc[mi][ni][2];
                smc[(ml + 8) * 17 + h_loc] = acc[mi][ni][3];
            }
        }
    }
    __syncthreads();
    for (int i = tid; i < 1024; i += 128) {
        int m = i >> 4, h = i & 15;
        size_t off = (size_t)(m0 + m) * 256 + h0 + h;
        float hv = smr[m * 17 + h];
        h_out[off] = hv;
        c_out[off] = smc[m * 17 + h];
        hH[off]    = f2h(hv);
    }
}

// ============================================================================
// GEMM template: MODE 0 encoder (BN=128), MODE 3 decoder (BN=32)
// ============================================================================
template<int MODE>
__global__ void __launch_bounds__(256, 2) gemm_f16(GP p) {
    constexpr int BN = (MODE == 3) ? 32 : 128;
    constexpr int WC = (MODE == 3) ? 1  : 4;
    constexpr int WR = 8 / WC;
    constexpr int MT = 8 / WR;
    constexpr int NT = 4;
    constexpr int K  = (MODE == 0) ? 128 : 256;
    constexpr int ITERS = K / 32;
    constexpr int WTM = MT * 16;
    constexpr int S   = 3;
    constexpr int AK  = (MODE == 0) ? 128 : 256;
    constexpr int BKH = K;
    constexpr uint32_t ASTAGE_B = 128 * 80;
    constexpr uint32_t BSTAGE_B = BN * 80;

    extern __shared__ uint32_t smem_u[];
    const uint32_t As_sh = (uint32_t)__cvta_generic_to_shared(smem_u);
    const uint32_t Bs_sh = As_sh + S * ASTAGE_B;

    const int tid  = threadIdx.x;
    const int lane = tid & 31, warp = tid >> 5;
    const int wr = warp / WC, wc = warp % WC;
    const int q  = lane & 3,  rr = lane >> 2;
    const int m0 = blockIdx.y * 128;
    const int bx = blockIdx.x;

    const int arow = tid >> 2;
    const int aseg = tid & 3;
    const uint32_t tOff = (uint32_t)(arow * 80 + aseg * 16);

    const uint16_t* pA = p.A + (size_t)(m0 + arow) * AK + aseg * 8;
    const uint16_t* pB;
    if constexpr (MODE == 0) pB = p.B0 + (size_t)(bx * 128 + arow) * 128 + aseg * 8;
    else                     pB = p.B0 + (size_t)arow * 256 + aseg * 8;

    auto issue = [&](int it, int s) {
        uint32_t ad = As_sh + (uint32_t)s * ASTAGE_B + tOff;
        uint32_t bd = Bs_sh + (uint32_t)s * BSTAGE_B + tOff;
        const uint16_t* a0 = pA + it * 32;
        cp16(ad, a0);
        cp16(ad + 64 * 80, a0 + (size_t)64 * AK);
        if constexpr (BN == 128) {
            cp16(bd, pB + it * 32);
            cp16(bd + 64 * 80, pB + (size_t)64 * BKH + it * 32);
        } else {
            if (tid < 128) cp16(bd, pB + it * 32);
        }
    };

    float acc[MT][NT][4];
    #pragma unroll
    for (int i = 0; i < MT; i++)
        #pragma unroll
        for (int j = 0; j < NT; j++)
            #pragma unroll
            for (int t = 0; t < 4; t++) acc[i][j][t] = 0.f;

    const int a_r = lane & 15, a_h = lane >> 4;
    const int b_g = lane >> 3, b_rl = lane & 7;
    const int b_row = (b_g >> 1) * 8 + b_rl;
    const int b_k16 = (b_g & 1) * 16;

    issue(0, 0); cp_commit();
    issue(1, 1); cp_commit();

    #pragma unroll
    for (int it = 0; it < ITERS; ++it) {
        const int s  = it % S;
        const int s2 = (it + 2) % S;
        cp_wait<1>();
        __syncthreads();
        if (it + 2 < ITERS) issue(it + 2, s2);
        cp_commit();

        const uint32_t Ab = As_sh + (uint32_t)s * ASTAGE_B;
        const uint32_t Bb = Bs_sh + (uint32_t)s * BSTAGE_B;
        #pragma unroll
        for (int ph = 0; ph < 2; ++ph) {
            uint32_t af[MT][4], bf[NT][2];
            #pragma unroll
            for (int mi = 0; mi < MT; ++mi)
                ldsm4(af[mi], Ab + (uint32_t)((wr * WTM + mi * 16 + a_r) * 80
                                              + ph * 32 + a_h * 16));
            #pragma unroll
            for (int pi = 0; pi < NT / 2; ++pi)
                ldsm4(&bf[2 * pi][0], Bb + (uint32_t)((wc * 32 + pi * 16 + b_row) * 80
                                                      + ph * 32 + b_k16));
            #pragma unroll
            for (int mi = 0; mi < MT; ++mi)
                #pragma unroll
                for (int ni = 0; ni < NT; ++ni)
                    mma16(acc[mi][ni], af[mi], bf[ni]);
        }
    }
    cp_wait<0>();
    __syncthreads();

    if constexpr (MODE == 0) {
        #pragma unroll
        for (int mi = 0; mi < MT; ++mi)
            #pragma unroll
            for (int ni = 0; ni < NT; ++ni) {
                int n = bx * 128 + wc * 32 + ni * 8 + q * 2;
                int m = m0 + wr * WTM + mi * 16 + rr;
                float b0v = p.bias0[n], b1v = p.bias0[n + 1];
                __half2 h0 = __floats2half2_rn(fmaxf(acc[mi][ni][0] + b0v, 0.f),
                                               fmaxf(acc[mi][ni][1] + b1v, 0.f));
                __half2 h1 = __floats2half2_rn(fmaxf(acc[mi][ni][2] + b0v, 0.f),
                                               fmaxf(acc[mi][ni][3] + b1v, 0.f));
                *(__half2*)(p.outH + (size_t)m * 256 + n) = h0;
                *(__half2*)(p.outH + (size_t)(m + 8) * 256 + n) = h1;
            }
    } else {
        #pragma unroll
        for (int mi = 0; mi < MT; ++mi)
            #pragma unroll
            for (int ni = 0; ni < NT; ++ni) {
                int n = ni * 8 + q * 2;
                int m = m0 + wr * WTM + mi * 16 + rr;
                float b0v = p.bias0[n], b1v = p.bias0[n + 1];
                *(float2*)(p.out0 + (size_t)m * 32 + n) =
                    make_float2(acc[mi][ni][0] + b0v, acc[mi][ni][1] + b1v);
                *(float2*)(p.out0 + (size_t)(m + 8) * 32 + n) =
                    make_float2(acc[mi][ni][2] + b0v, acc[mi][ni][3] + b1v);
            }
    }
}

// ---------------- pack prologue: split main vs hid ---------------------------
__global__ void pack_main_kernel(const float* __restrict__ mo,
                                 const float* __restrict__ Wenc,
                                 const float* __restrict__ Wq, const float* __restrict__ Wk,
                                 const float* __restrict__ Wv,
                                 const float* __restrict__ Wih, const float* __restrict__ Whh,
                                 const float* __restrict__ Wdec,
                                 uint16_t* __restrict__ moH,
                                 uint16_t* __restrict__ wencH, uint16_t* __restrict__ wqkvH,
                                 uint16_t* __restrict__ wcatH, uint16_t* __restrict__ wdecH)
{
    const int stride = gridDim.x * blockDim.x;
    const int g = blockIdx.x * blockDim.x + threadIdx.x;
    auto cvt4 = [](float4 v) -> uint2 {
        __half2 h01 = __floats2half2_rn(v.x, v.y);
        __half2 h23 = __floats2half2_rn(v.z, v.w);
        return make_uint2(*(uint32_t*)&h01, *(uint32_t*)&h23);
    };
    {
        const float4* s4 = (const float4*)mo;
        uint2* d4 = (uint2*)moH;
        for (size_t i = g; i < (size_t)NB * 128 / 4; i += stride) d4[i] = cvt4(s4[i]);
    }
    for (int i = g; i < 256 * 128; i += stride) wencH[i] = f2h(Wenc[i]);
    for (int i = g; i < 64 * 256; i += stride) {
        wqkvH[i]         = f2h(Wq[i]);
        wqkvH[16384 + i] = f2h(Wk[i]);
        wqkvH[32768 + i] = f2h(Wv[i]);
    }
    for (int i = g; i < 1024 * 448; i += stride) {
        int n = i / 448, k = i - n * 448;
        int h = n >> 2, gg = n & 3, r = gg * 256 + h;
        float v = (k < 192) ? Wih[(size_t)r * 192 + k] : Whh[(size_t)r * 256 + (k - 192)];
        wcatH[i] = f2h(v);
    }
    for (int i = g; i < 32 * 256; i += stride) wdecH[i] = f2h(Wdec[i]);
}

__global__ void pack_hid_kernel(const float* __restrict__ hid,
                                uint16_t* __restrict__ hidH)
{
    const int stride = gridDim.x * blockDim.x;
    const int g = blockIdx.x * blockDim.x + threadIdx.x;
    const float4* s4 = (const float4*)hid;
    uint2* d4 = (uint2*)hidH;
    for (size_t i = g; i < (size_t)NB * 256 / 4; i += stride) {
        float4 v = s4[i];
        __half2 h01 = __floats2half2_rn(v.x, v.y);
        __half2 h23 = __floats2half2_rn(v.z, v.w);
        d4[i] = make_uint2(*(uint32_t*)&h01, *(uint32_t*)&h23);
    }
}

// ---------------- launch ----------------------------------------------------
extern "C" void kernel_launch(void* const* d_in, const int* in_sizes, int n_in,
                              void* d_out, int out_size)
{
    const float* mo    = (const float*)d_in[0];
    const float* hid   = (const float*)d_in[1];
    const float* cell  = (const float*)d_in[2];
    const float* Wenc  = (const float*)d_in[3];
    const float* benc  = (const float*)d_in[4];
    const float* Wq    = (const float*)d_in[5];
    const float* Wk    = (const float*)d_in[6];
    const float* Wv    = (const float*)d_in[7];
    const float* bv    = (const float*)d_in[8];
    const float* Wih   = (const float*)d_in[9];
    const float* Whh   = (const float*)d_in[10];
    const float* bih   = (const float*)d_in[11];
    const float* bhh   = (const float*)d_in[12];
    const float* Wdec  = (const float*)d_in[13];
    const float* bdec  = (const float*)d_in[14];

    float* out   = (float*)d_out;
    float* m_act = out;
    float* h_out = out + (size_t)NB * NA_DIM;
    float* c_out = h_out + (size_t)NB * H_DIM;

    uint16_t *moH, *hidH, *xH, *eH, *hH, *wencH, *wqkvH, *wcatH, *wdecH;
    cudaGetSymbolAddress((void**)&moH,   g_moH);
    cudaGetSymbolAddress((void**)&hidH,  g_hidH);
    cudaGetSymbolAddress((void**)&xH,    g_xH);
    cudaGetSymbolAddress((void**)&eH,    g_eH);
    cudaGetSymbolAddress((void**)&hH,    g_hH);
    cudaGetSymbolAddress((void**)&wencH, g_wencH);
    cudaGetSymbolAddress((void**)&wqkvH, g_wqkvH);
    cudaGetSymbolAddress((void**)&wcatH, g_wcatH);
    cudaGetSymbolAddress((void**)&wdecH, g_wdecH);

    cudaFuncSetAttribute(gemm_f16<0>, cudaFuncAttributeMaxDynamicSharedMemorySize, 61440);
    cudaFuncSetAttribute(gemm_f16<3>, cudaFuncAttributeMaxDynamicSharedMemorySize, 38400);
    cudaFuncSetAttribute(gates_kernel, cudaFuncAttributeMaxDynamicSharedMemorySize,
                         G_S * G_STAGE);                 // 30720
    cudaFuncSetAttribute(qkv_attn_kernel, cudaFuncAttributeMaxDynamicSharedMemorySize, QK_SMEM);

    // side stream for hid packing (non-blocking: no implicit legacy sync)
    cudaStream_t s2;
    cudaStreamCreateWithFlags(&s2, cudaStreamNonBlocking);
    cudaEvent_t e_fork, e_join;
    cudaEventCreateWithFlags(&e_fork, cudaEventDisableTiming);
    cudaEventCreateWithFlags(&e_join, cudaEventDisableTiming);

    // fork: hid pack runs concurrently with pack_main/encoder/qkv
    cudaEventRecord(e_fork, 0);
    cudaStreamWaitEvent(s2, e_fork, 0);
    pack_hid_kernel<<<2048, 256, 0, s2>>>(hid, hidH);
    cudaEventRecord(e_join, s2);

    // 0) pack mo + weights (default stream)
    pack_main_kernel<<<2048, 256>>>(mo, Wenc, Wq, Wk, Wv, Wih, Whh, Wdec,
                                    moH, wencH, wqkvH, wcatH, wdecH);
    // 1) encoder
    {
        GP p{}; p.A = moH; p.B0 = wencH; p.bias0 = benc; p.outH = xH;
        gemm_f16<0><<<dim3(2, 1024), 256, 61440>>>(p);
    }
    // 2) fused qkv + attention -> eH (64-row CTAs, 2 CTAs/SM)
    qkv_attn_kernel<<<2048, 256, QK_SMEM>>>(xH, wqkvH, bv, eH);

    // join: gates needs hidH
    cudaStreamWaitEvent(0, e_join, 0);

    // 3) gates GEMM (64x64 tiles, 7 CTAs/SM, S=3) + fused LSTM
    gates_kernel<<<dim3(16, 2048), 128, G_S * G_STAGE>>>(
        moH, eH, hidH, wcatH, bih, bhh, cell, h_out, c_out, hH);
    // 4) decoder
    {
        GP p{}; p.A = hH; p.B0 = wdecH; p.bias0 = bdec; p.out0 = m_act;
        gemm_f16<3><<<dim3(1, 1024), 256, 38400>>>(p);
    }
}